// round 5
// baseline (speedup 1.0000x reference)
#include <cuda_runtime.h>
#include <cuda_bf16.h>

#define N_NODES 50000
#define E_EDGES 800000
#define IN_C    16
#define HDIM    64
#define HH      32
#define NLAYERS 3
#define FULL    0xffffffffu

// Scratch (device globals)
__device__ float  g_h[N_NODES * HDIM];   // row-major [n][64]
__device__ float4 g_p4[N_NODES * 8];     // row-major [n][32]
__device__ float4 g_q4[N_NODES * 8];     // row-major [n][32] (mean-scaled relu sums)
__device__ int    g_deg[N_NODES];
__device__ int    g_start[N_NODES];
__device__ int    g_cursor[N_NODES];
__device__ int    g_total;
__device__ float4 g_eperm[E_EDGES];      // [src_bits, e0, e1, e2] bucketed by dst

// ---------------- encoder: h + p0 + zero deg ----------------
__global__ __launch_bounds__(256) void encoder_kernel(
    const float* __restrict__ x,  const float* __restrict__ w,
    const float* __restrict__ b,  const float* __restrict__ g,
    const float* __restrict__ beta,
    const float* __restrict__ w1, const float* __restrict__ b1)
{
    int warp = (blockIdx.x * blockDim.x + threadIdx.x) >> 5;
    int lane = threadIdx.x & 31;
    int n0   = warp * 4;
    if (n0 >= N_NODES) return;

    float* g_p = (float*)g_p4;

    float xv[4], a0[4], a1[4];
#pragma unroll
    for (int i = 0; i < 4; i++) {
        xv[i] = (lane < IN_C) ? x[(n0 + i) * IN_C + lane] : 0.0f;
        a0[i] = __ldg(&b[lane]);
        a1[i] = __ldg(&b[lane + 32]);
    }
#pragma unroll
    for (int k = 0; k < IN_C; k++) {
        float w0 = __ldg(&w[k * HDIM + lane]);
        float w1v = __ldg(&w[k * HDIM + 32 + lane]);
#pragma unroll
        for (int i = 0; i < 4; i++) {
            float xk = __shfl_sync(FULL, xv[i], k);
            a0[i] = fmaf(xk, w0, a0[i]);
            a1[i] = fmaf(xk, w1v, a1[i]);
        }
    }
    float gl = __ldg(&g[lane]), gh = __ldg(&g[lane + 32]);
    float bl = __ldg(&beta[lane]), bh = __ldg(&beta[lane + 32]);
    float h0[4], h1[4];
#pragma unroll
    for (int i = 0; i < 4; i++) {
        float s1 = a0[i] + a1[i], s2 = a0[i] * a0[i] + a1[i] * a1[i];
#pragma unroll
        for (int o = 16; o; o >>= 1) {
            s1 += __shfl_xor_sync(FULL, s1, o);
            s2 += __shfl_xor_sync(FULL, s2, o);
        }
        float mu  = s1 * (1.0f / 64.0f);
        float var = s2 * (1.0f / 64.0f) - mu * mu;
        float rs  = rsqrtf(var + 1e-5f);
        h0[i] = fmaxf(fmaf((a0[i] - mu) * rs, gl, bl), 0.0f);
        h1[i] = fmaxf(fmaf((a1[i] - mu) * rs, gh, bh), 0.0f);
        g_h[(n0 + i) * HDIM + lane]      = h0[i];
        g_h[(n0 + i) * HDIM + 32 + lane] = h1[i];
    }
    float acc[4];
#pragma unroll
    for (int i = 0; i < 4; i++) acc[i] = __ldg(&b1[lane]);
#pragma unroll
    for (int k = 0; k < 32; k++) {
        float wk = __ldg(&w1[k * HH + lane]);
#pragma unroll
        for (int i = 0; i < 4; i++)
            acc[i] = fmaf(__shfl_sync(FULL, h0[i], k), wk, acc[i]);
    }
#pragma unroll
    for (int k = 0; k < 32; k++) {
        float wk = __ldg(&w1[(32 + k) * HH + lane]);
#pragma unroll
        for (int i = 0; i < 4; i++)
            acc[i] = fmaf(__shfl_sync(FULL, h1[i], k), wk, acc[i]);
    }
#pragma unroll
    for (int i = 0; i < 4; i++)
        g_p[(n0 + i) * HH + lane] = acc[i];
    if (lane < 4) g_deg[n0 + lane] = 0;
}

// ---------------- CSR build ----------------
__global__ void count_kernel(const int* __restrict__ ei) {
    int e = blockIdx.x * blockDim.x + threadIdx.x;
    if (e < E_EDGES) atomicAdd(&g_deg[ei[E_EDGES + e]], 1);
}

__global__ void zero_total_kernel() { if (threadIdx.x == 0) g_total = 0; }

__global__ void assign_kernel() {
    int n = blockIdx.x * blockDim.x + threadIdx.x;
    if (n >= N_NODES) return;
    int d = g_deg[n];
    int s = (d > 0) ? atomicAdd(&g_total, d) : 0;
    g_start[n]  = s;
    g_cursor[n] = s;
}

__global__ void bucket_kernel(const int* __restrict__ ei, const float* __restrict__ ea) {
    int e = blockIdx.x * blockDim.x + threadIdx.x;
    if (e >= E_EDGES) return;
    int src = __ldg(&ei[e]);
    int dst = __ldg(&ei[E_EDGES + e]);
    int pos = atomicAdd(&g_cursor[dst], 1);
    g_eperm[pos] = make_float4(__int_as_float(src),
                               __ldg(&ea[e * 3 + 0]),
                               __ldg(&ea[e * 3 + 1]),
                               __ldg(&ea[e * 3 + 2]));
}

// ---------------- per-layer edge gather: q[d] = mean_e relu(p[src]+ea@We) ----------------
__global__ __launch_bounds__(256) void edge_gather_kernel(const float* __restrict__ w1)
{
    int d = (blockIdx.x * blockDim.x + threadIdx.x) >> 5;
    int lane = threadIdx.x & 31;
    if (d >= N_NODES) return;
    int quad = lane & 7, grp = lane >> 3;

    int start = g_start[d];
    int deg   = g_deg[d];

    const float4* W = (const float4*)(w1 + 64 * HH);
    float4 wa = __ldg(&W[quad]);
    float4 wb = __ldg(&W[8 + quad]);
    float4 wc = __ldg(&W[16 + quad]);

    float4 acc = make_float4(0.f, 0.f, 0.f, 0.f);
    for (int c = grp; c < deg; c += 4) {
        float4 m = __ldg(&g_eperm[start + c]);
        int src = __float_as_int(m.x);
        float4 p = __ldg(&g_p4[src * 8 + quad]);
        acc.x += fmaxf(fmaf(m.w, wc.x, fmaf(m.z, wb.x, fmaf(m.y, wa.x, p.x))), 0.f);
        acc.y += fmaxf(fmaf(m.w, wc.y, fmaf(m.z, wb.y, fmaf(m.y, wa.y, p.y))), 0.f);
        acc.z += fmaxf(fmaf(m.w, wc.z, fmaf(m.z, wb.z, fmaf(m.y, wa.z, p.z))), 0.f);
        acc.w += fmaxf(fmaf(m.w, wc.w, fmaf(m.z, wb.w, fmaf(m.y, wa.w, p.w))), 0.f);
    }
    // reduce the 4 groups (lanes differing in bits 3,4)
#pragma unroll
    for (int off = 8; off <= 16; off <<= 1) {
        acc.x += __shfl_xor_sync(FULL, acc.x, off);
        acc.y += __shfl_xor_sync(FULL, acc.y, off);
        acc.z += __shfl_xor_sync(FULL, acc.z, off);
        acc.w += __shfl_xor_sync(FULL, acc.w, off);
    }
    if (grp == 0) {
        float inv = (deg > 0) ? (1.f / (float)deg) : 0.f;
        g_q4[d * 8 + quad] = make_float4(acc.x * inv, acc.y * inv, acc.z * inv, acc.w * inv);
    }
}

// ---- stage-2 + mean + residual + LN; transposed-smem broadcast; LAST fuses heads ----
template<bool LAST>
__global__ __launch_bounds__(256) void node_agg_kernel(
    const float* __restrict__ w2,  const float* __restrict__ b2,
    const float* __restrict__ g,   const float* __restrict__ beta,
    const float* __restrict__ w1n, const float* __restrict__ b1n,
    const float* __restrict__ dw1, const float* __restrict__ db1,
    const float* __restrict__ dw2, const float* __restrict__ db2,
    const float* __restrict__ vw1, const float* __restrict__ vb1,
    const float* __restrict__ vw2, const float* __restrict__ vb2,
    float* __restrict__ out)
{
    __shared__ float sbuf[64 * 36];   // [k][node], stride 36
    int t = threadIdx.x, w = t >> 5, lane = t & 31;
    int n0 = blockIdx.x * 32;
    int rem = N_NODES - n0; if (rem > 32) rem = 32;

    // stage q transposed (already mean-scaled)
    {
        int nl = t >> 3, k0 = (t & 7) << 2;
        float4 v = make_float4(0.f, 0.f, 0.f, 0.f);
        if (nl < rem) v = g_q4[(size_t)n0 * 8 + t];
        sbuf[(k0 + 0) * 36 + nl] = v.x;
        sbuf[(k0 + 1) * 36 + nl] = v.y;
        sbuf[(k0 + 2) * 36 + nl] = v.z;
        sbuf[(k0 + 3) * 36 + nl] = v.w;
    }
    __syncthreads();

    int nb = w * 4;

    float o0[4] = {0, 0, 0, 0}, o1[4] = {0, 0, 0, 0};
#pragma unroll
    for (int k = 0; k < 32; k++) {
        float4 qv = *(const float4*)&sbuf[k * 36 + nb];
        float wlo = __ldg(&w2[k * HDIM + lane]);
        float whi = __ldg(&w2[k * HDIM + 32 + lane]);
        o0[0] = fmaf(qv.x, wlo, o0[0]); o1[0] = fmaf(qv.x, whi, o1[0]);
        o0[1] = fmaf(qv.y, wlo, o0[1]); o1[1] = fmaf(qv.y, whi, o1[1]);
        o0[2] = fmaf(qv.z, wlo, o0[2]); o1[2] = fmaf(qv.z, whi, o1[2]);
        o0[3] = fmaf(qv.w, wlo, o0[3]); o1[3] = fmaf(qv.w, whi, o1[3]);
    }
    float b2l = __ldg(&b2[lane]),  b2h = __ldg(&b2[32 + lane]);
    float gl  = __ldg(&g[lane]),   gh  = __ldg(&g[lane + 32]);
    float bl  = __ldg(&beta[lane]), bh = __ldg(&beta[lane + 32]);

    float h0[4], h1[4];
#pragma unroll
    for (int i = 0; i < 4; i++) {
        int n = n0 + nb + i;
        bool act = (nb + i) < rem;
        float has = (act && g_deg[n] > 0) ? 1.f : 0.f;
        float hh0 = act ? g_h[(size_t)n * HDIM + lane] : 0.f;
        float hh1 = act ? g_h[(size_t)n * HDIM + 32 + lane] : 0.f;
        float a0 = hh0 + o0[i] + has * b2l;
        float a1 = hh1 + o1[i] + has * b2h;
        float s1 = a0 + a1, s2 = a0 * a0 + a1 * a1;
#pragma unroll
        for (int o = 16; o; o >>= 1) {
            s1 += __shfl_xor_sync(FULL, s1, o);
            s2 += __shfl_xor_sync(FULL, s2, o);
        }
        float mu  = s1 * (1.f / 64.f);
        float var = s2 * (1.f / 64.f) - mu * mu;
        float rs  = rsqrtf(var + 1e-5f);
        h0[i] = fmaf((a0 - mu) * rs, gl, bl);
        h1[i] = fmaf((a1 - mu) * rs, gh, bh);
        if (!LAST && act) {
            g_h[(size_t)n * HDIM + lane]      = h0[i];
            g_h[(size_t)n * HDIM + 32 + lane] = h1[i];
        }
    }
    __syncthreads();

#pragma unroll
    for (int i = 0; i < 4; i++) {
        sbuf[lane * 36 + nb + i]        = h0[i];
        sbuf[(lane + 32) * 36 + nb + i] = h1[i];
    }
    __syncthreads();

    if (!LAST) {
        float pacc[4];
        float bb = __ldg(&b1n[lane]);
#pragma unroll
        for (int i = 0; i < 4; i++) pacc[i] = bb;
#pragma unroll
        for (int k = 0; k < 64; k++) {
            float4 hv = *(const float4*)&sbuf[k * 36 + nb];
            float wk = __ldg(&w1n[k * HH + lane]);
            pacc[0] = fmaf(hv.x, wk, pacc[0]);
            pacc[1] = fmaf(hv.y, wk, pacc[1]);
            pacc[2] = fmaf(hv.z, wk, pacc[2]);
            pacc[3] = fmaf(hv.w, wk, pacc[3]);
        }
        float* gp = (float*)g_p4;
#pragma unroll
        for (int i = 0; i < 4; i++)
            if ((nb + i) < rem) gp[(size_t)(n0 + nb + i) * HH + lane] = pacc[i];
    } else {
        float da[4], va[4];
        float dbi = __ldg(&db1[lane]), vbi = __ldg(&vb1[lane]);
#pragma unroll
        for (int i = 0; i < 4; i++) { da[i] = dbi; va[i] = vbi; }
#pragma unroll
        for (int k = 0; k < 64; k++) {
            float4 hv = *(const float4*)&sbuf[k * 36 + nb];
            float dwk = __ldg(&dw1[k * HH + lane]);
            float vwk = __ldg(&vw1[k * HH + lane]);
            da[0] = fmaf(hv.x, dwk, da[0]); va[0] = fmaf(hv.x, vwk, va[0]);
            da[1] = fmaf(hv.y, dwk, da[1]); va[1] = fmaf(hv.y, vwk, va[1]);
            da[2] = fmaf(hv.z, dwk, da[2]); va[2] = fmaf(hv.z, vwk, va[2]);
            da[3] = fmaf(hv.w, dwk, da[3]); va[3] = fmaf(hv.w, vwk, va[3]);
        }
        float w2d  = __ldg(&dw2[lane]);
        float w2v0 = __ldg(&vw2[lane * 2 + 0]);
        float w2v1 = __ldg(&vw2[lane * 2 + 1]);
#pragma unroll
        for (int i = 0; i < 4; i++) {
            float rd = fmaxf(da[i], 0.f), rv = fmaxf(va[i], 0.f);
            float d  = rd * w2d;
            float v0 = rv * w2v0;
            float v1 = rv * w2v1;
#pragma unroll
            for (int o = 16; o; o >>= 1) {
                d  += __shfl_xor_sync(FULL, d, o);
                v0 += __shfl_xor_sync(FULL, v0, o);
                v1 += __shfl_xor_sync(FULL, v1, o);
            }
            int n = n0 + nb + i;
            if (lane == 0 && (nb + i) < rem) {
                out[n] = d + __ldg(&db2[0]);
                float2* vout = (float2*)(out + N_NODES);
                vout[n] = make_float2(v0 + __ldg(&vb2[0]), v1 + __ldg(&vb2[1]));
            }
        }
    }
}

// ---------------- launch ----------------
extern "C" void kernel_launch(void* const* d_in, const int* in_sizes, int n_in,
                              void* d_out, int out_size)
{
    const float* x       = (const float*)d_in[0];
    const int*   ei      = (const int*)  d_in[1];
    const float* ea      = (const float*)d_in[2];
    const float* enc_w   = (const float*)d_in[3];
    const float* enc_b   = (const float*)d_in[4];
    const float* enc_g   = (const float*)d_in[5];
    const float* enc_bt  = (const float*)d_in[6];
    const float* mlp_w1  = (const float*)d_in[7];   // [L, 67, 32]
    const float* mlp_b1  = (const float*)d_in[8];   // [L, 32]
    const float* mlp_w2  = (const float*)d_in[9];   // [L, 32, 64]
    const float* mlp_b2  = (const float*)d_in[10];  // [L, 64]
    const float* ln_g    = (const float*)d_in[11];  // [L, 64]
    const float* ln_b    = (const float*)d_in[12];  // [L, 64]
    const float* dw1     = (const float*)d_in[13];
    const float* db1     = (const float*)d_in[14];
    const float* dw2     = (const float*)d_in[15];
    const float* db2     = (const float*)d_in[16];
    const float* vw1     = (const float*)d_in[17];
    const float* vb1     = (const float*)d_in[18];
    const float* vw2     = (const float*)d_in[19];
    const float* vb2     = (const float*)d_in[20];
    float* out = (float*)d_out;

    const int TB = 256;
    const int enc_grid  = (N_NODES / 4 * 32 + TB - 1) / TB;   // 4 nodes/warp
    const int node_grid = (N_NODES + 31) / 32;                // 32 nodes/block
    const int gath_grid = (N_NODES * 32 + TB - 1) / TB;       // warp/node
    const int eTB_grid  = (E_EDGES + TB - 1) / TB;

    encoder_kernel<<<enc_grid, TB>>>(x, enc_w, enc_b, enc_g, enc_bt,
                                     mlp_w1, mlp_b1);
    count_kernel<<<eTB_grid, TB>>>(ei);
    zero_total_kernel<<<1, 32>>>();
    assign_kernel<<<(N_NODES + TB - 1) / TB, TB>>>();
    bucket_kernel<<<eTB_grid, TB>>>(ei, ea);

    for (int i = 0; i < NLAYERS; i++) {
        const float* w1 = mlp_w1 + (size_t)i * (HDIM + 3) * HH;
        const float* w2 = mlp_w2 + (size_t)i * HH * HDIM;
        const float* b2 = mlp_b2 + (size_t)i * HDIM;
        const float* lg = ln_g   + (size_t)i * HDIM;
        const float* lb = ln_b   + (size_t)i * HDIM;
        const float* w1n = mlp_w1 + (size_t)(i + 1) * (HDIM + 3) * HH;
        const float* b1n = mlp_b1 + (size_t)(i + 1) * HH;

        edge_gather_kernel<<<gath_grid, TB>>>(w1);

        if (i + 1 < NLAYERS)
            node_agg_kernel<false><<<node_grid, TB>>>(w2, b2, lg, lb, w1n, b1n,
                dw1, db1, dw2, db2, vw1, vb1, vw2, vb2, out);
        else
            node_agg_kernel<true ><<<node_grid, TB>>>(w2, b2, lg, lb, nullptr, nullptr,
                dw1, db1, dw2, db2, vw1, vb1, vw2, vb2, out);
    }
}

// round 6
// speedup vs baseline: 1.0255x; 1.0255x over previous
#include <cuda_runtime.h>
#include <cuda_bf16.h>

#define N_NODES 50000
#define E_EDGES 800000
#define IN_C    16
#define HDIM    64
#define HH      32
#define NLAYERS 3
#define FULL    0xffffffffu

// Scratch (device globals)
__device__ float  g_h[N_NODES * HDIM];   // row-major [n][64]
__device__ float4 g_p4[N_NODES * 8];     // row-major [n][32]
__device__ float4 g_q4[N_NODES * 8];     // row-major [n][32] (mean-scaled relu sums)
__device__ int    g_deg[N_NODES];
__device__ int    g_start[N_NODES];
__device__ int    g_cursor[N_NODES];
__device__ int    g_total;
__device__ float4 g_eperm[E_EDGES];      // [src_bits, e0, e1, e2] bucketed by dst

// ---------------- encoder: h + p0 + zero deg ----------------
__global__ __launch_bounds__(256) void encoder_kernel(
    const float* __restrict__ x,  const float* __restrict__ w,
    const float* __restrict__ b,  const float* __restrict__ g,
    const float* __restrict__ beta,
    const float* __restrict__ w1, const float* __restrict__ b1)
{
    int warp = (blockIdx.x * blockDim.x + threadIdx.x) >> 5;
    int lane = threadIdx.x & 31;
    int n0   = warp * 4;
    if (n0 >= N_NODES) return;

    float* g_p = (float*)g_p4;

    float xv[4], a0[4], a1[4];
#pragma unroll
    for (int i = 0; i < 4; i++) {
        xv[i] = (lane < IN_C) ? x[(n0 + i) * IN_C + lane] : 0.0f;
        a0[i] = __ldg(&b[lane]);
        a1[i] = __ldg(&b[lane + 32]);
    }
#pragma unroll
    for (int k = 0; k < IN_C; k++) {
        float w0 = __ldg(&w[k * HDIM + lane]);
        float w1v = __ldg(&w[k * HDIM + 32 + lane]);
#pragma unroll
        for (int i = 0; i < 4; i++) {
            float xk = __shfl_sync(FULL, xv[i], k);
            a0[i] = fmaf(xk, w0, a0[i]);
            a1[i] = fmaf(xk, w1v, a1[i]);
        }
    }
    float gl = __ldg(&g[lane]), gh = __ldg(&g[lane + 32]);
    float bl = __ldg(&beta[lane]), bh = __ldg(&beta[lane + 32]);
    float h0[4], h1[4];
#pragma unroll
    for (int i = 0; i < 4; i++) {
        float s1 = a0[i] + a1[i], s2 = a0[i] * a0[i] + a1[i] * a1[i];
#pragma unroll
        for (int o = 16; o; o >>= 1) {
            s1 += __shfl_xor_sync(FULL, s1, o);
            s2 += __shfl_xor_sync(FULL, s2, o);
        }
        float mu  = s1 * (1.0f / 64.0f);
        float var = s2 * (1.0f / 64.0f) - mu * mu;
        float rs  = rsqrtf(var + 1e-5f);
        h0[i] = fmaxf(fmaf((a0[i] - mu) * rs, gl, bl), 0.0f);
        h1[i] = fmaxf(fmaf((a1[i] - mu) * rs, gh, bh), 0.0f);
        g_h[(n0 + i) * HDIM + lane]      = h0[i];
        g_h[(n0 + i) * HDIM + 32 + lane] = h1[i];
    }
    float acc[4];
#pragma unroll
    for (int i = 0; i < 4; i++) acc[i] = __ldg(&b1[lane]);
#pragma unroll
    for (int k = 0; k < 32; k++) {
        float wk = __ldg(&w1[k * HH + lane]);
#pragma unroll
        for (int i = 0; i < 4; i++)
            acc[i] = fmaf(__shfl_sync(FULL, h0[i], k), wk, acc[i]);
    }
#pragma unroll
    for (int k = 0; k < 32; k++) {
        float wk = __ldg(&w1[(32 + k) * HH + lane]);
#pragma unroll
        for (int i = 0; i < 4; i++)
            acc[i] = fmaf(__shfl_sync(FULL, h1[i], k), wk, acc[i]);
    }
#pragma unroll
    for (int i = 0; i < 4; i++)
        g_p[(n0 + i) * HH + lane] = acc[i];
    if (lane < 4) g_deg[n0 + lane] = 0;
}

// ---------------- CSR build ----------------
__global__ void count_kernel(const int* __restrict__ ei) {
    int e = blockIdx.x * blockDim.x + threadIdx.x;
    if (e < E_EDGES) atomicAdd(&g_deg[ei[E_EDGES + e]], 1);
}

__global__ void zero_total_kernel() { if (threadIdx.x == 0) g_total = 0; }

__global__ void assign_kernel() {
    int n = blockIdx.x * blockDim.x + threadIdx.x;
    if (n >= N_NODES) return;
    int d = g_deg[n];
    int s = (d > 0) ? atomicAdd(&g_total, d) : 0;
    g_start[n]  = s;
    g_cursor[n] = s;
}

__global__ void bucket_kernel(const int* __restrict__ ei, const float* __restrict__ ea) {
    int e = blockIdx.x * blockDim.x + threadIdx.x;
    if (e >= E_EDGES) return;
    int src = __ldg(&ei[e]);
    int dst = __ldg(&ei[E_EDGES + e]);
    int pos = atomicAdd(&g_cursor[dst], 1);
    g_eperm[pos] = make_float4(__int_as_float(src),
                               __ldg(&ea[e * 3 + 0]),
                               __ldg(&ea[e * 3 + 1]),
                               __ldg(&ea[e * 3 + 2]));
}

// ---- per-layer edge gather: q[d] = mean_e relu(p[src]+ea@We); 4-edge batched MLP ----
__global__ __launch_bounds__(256) void edge_gather_kernel(const float* __restrict__ w1)
{
    int d = (blockIdx.x * blockDim.x + threadIdx.x) >> 5;
    int lane = threadIdx.x & 31;
    if (d >= N_NODES) return;
    int quad = lane & 7, grp = lane >> 3;

    int start = g_start[d];
    int deg   = g_deg[d];

    const float4* W = (const float4*)(w1 + 64 * HH);
    float4 wa = __ldg(&W[quad]);
    float4 wb = __ldg(&W[8 + quad]);
    float4 wc = __ldg(&W[16 + quad]);

    const float4 z = make_float4(0.f, 0.f, 0.f, 0.f);
    float4 acc = z;

    // group grp owns edge slots [grp*4 + 16*t, grp*4 + 16*t + 4)
    for (int c0 = grp * 4; c0 < deg; c0 += 16) {
        float4 m[4], p[4];
#pragma unroll
        for (int j = 0; j < 4; j++)
            m[j] = (c0 + j < deg) ? __ldg(&g_eperm[start + c0 + j]) : z;
#pragma unroll
        for (int j = 0; j < 4; j++) {
            int src = __float_as_int(m[j].x);
            p[j] = (c0 + j < deg) ? __ldg(&g_p4[src * 8 + quad]) : z;
        }
#pragma unroll
        for (int j = 0; j < 4; j++) {
            acc.x += fmaxf(fmaf(m[j].w, wc.x, fmaf(m[j].z, wb.x, fmaf(m[j].y, wa.x, p[j].x))), 0.f);
            acc.y += fmaxf(fmaf(m[j].w, wc.y, fmaf(m[j].z, wb.y, fmaf(m[j].y, wa.y, p[j].y))), 0.f);
            acc.z += fmaxf(fmaf(m[j].w, wc.z, fmaf(m[j].z, wb.z, fmaf(m[j].y, wa.z, p[j].z))), 0.f);
            acc.w += fmaxf(fmaf(m[j].w, wc.w, fmaf(m[j].z, wb.w, fmaf(m[j].y, wa.w, p[j].w))), 0.f);
        }
    }
    // reduce the 4 groups (lanes differing in bits 3,4)
#pragma unroll
    for (int off = 8; off <= 16; off <<= 1) {
        acc.x += __shfl_xor_sync(FULL, acc.x, off);
        acc.y += __shfl_xor_sync(FULL, acc.y, off);
        acc.z += __shfl_xor_sync(FULL, acc.z, off);
        acc.w += __shfl_xor_sync(FULL, acc.w, off);
    }
    if (grp == 0) {
        float inv = (deg > 0) ? (1.f / (float)deg) : 0.f;
        g_q4[d * 8 + quad] = make_float4(acc.x * inv, acc.y * inv, acc.z * inv, acc.w * inv);
    }
}

// ---- stage-2 + mean + residual + LN; transposed-smem broadcast; LAST fuses heads ----
template<bool LAST>
__global__ __launch_bounds__(256) void node_agg_kernel(
    const float* __restrict__ w2,  const float* __restrict__ b2,
    const float* __restrict__ g,   const float* __restrict__ beta,
    const float* __restrict__ w1n, const float* __restrict__ b1n,
    const float* __restrict__ dw1, const float* __restrict__ db1,
    const float* __restrict__ dw2, const float* __restrict__ db2,
    const float* __restrict__ vw1, const float* __restrict__ vb1,
    const float* __restrict__ vw2, const float* __restrict__ vb2,
    float* __restrict__ out)
{
    __shared__ float sbuf[64 * 36];   // [k][node], stride 36
    int t = threadIdx.x, w = t >> 5, lane = t & 31;
    int n0 = blockIdx.x * 32;
    int rem = N_NODES - n0; if (rem > 32) rem = 32;

    // stage q transposed (already mean-scaled)
    {
        int nl = t >> 3, k0 = (t & 7) << 2;
        float4 v = make_float4(0.f, 0.f, 0.f, 0.f);
        if (nl < rem) v = g_q4[(size_t)n0 * 8 + t];
        sbuf[(k0 + 0) * 36 + nl] = v.x;
        sbuf[(k0 + 1) * 36 + nl] = v.y;
        sbuf[(k0 + 2) * 36 + nl] = v.z;
        sbuf[(k0 + 3) * 36 + nl] = v.w;
    }
    __syncthreads();

    int nb = w * 4;

    float o0[4] = {0, 0, 0, 0}, o1[4] = {0, 0, 0, 0};
#pragma unroll
    for (int k = 0; k < 32; k++) {
        float4 qv = *(const float4*)&sbuf[k * 36 + nb];
        float wlo = __ldg(&w2[k * HDIM + lane]);
        float whi = __ldg(&w2[k * HDIM + 32 + lane]);
        o0[0] = fmaf(qv.x, wlo, o0[0]); o1[0] = fmaf(qv.x, whi, o1[0]);
        o0[1] = fmaf(qv.y, wlo, o0[1]); o1[1] = fmaf(qv.y, whi, o1[1]);
        o0[2] = fmaf(qv.z, wlo, o0[2]); o1[2] = fmaf(qv.z, whi, o1[2]);
        o0[3] = fmaf(qv.w, wlo, o0[3]); o1[3] = fmaf(qv.w, whi, o1[3]);
    }
    float b2l = __ldg(&b2[lane]),  b2h = __ldg(&b2[32 + lane]);
    float gl  = __ldg(&g[lane]),   gh  = __ldg(&g[lane + 32]);
    float bl  = __ldg(&beta[lane]), bh = __ldg(&beta[lane + 32]);

    float h0[4], h1[4];
#pragma unroll
    for (int i = 0; i < 4; i++) {
        int n = n0 + nb + i;
        bool act = (nb + i) < rem;
        float has = (act && g_deg[n] > 0) ? 1.f : 0.f;
        float hh0 = act ? g_h[(size_t)n * HDIM + lane] : 0.f;
        float hh1 = act ? g_h[(size_t)n * HDIM + 32 + lane] : 0.f;
        float a0 = hh0 + o0[i] + has * b2l;
        float a1 = hh1 + o1[i] + has * b2h;
        float s1 = a0 + a1, s2 = a0 * a0 + a1 * a1;
#pragma unroll
        for (int o = 16; o; o >>= 1) {
            s1 += __shfl_xor_sync(FULL, s1, o);
            s2 += __shfl_xor_sync(FULL, s2, o);
        }
        float mu  = s1 * (1.f / 64.f);
        float var = s2 * (1.f / 64.f) - mu * mu;
        float rs  = rsqrtf(var + 1e-5f);
        h0[i] = fmaf((a0 - mu) * rs, gl, bl);
        h1[i] = fmaf((a1 - mu) * rs, gh, bh);
        if (!LAST && act) {
            g_h[(size_t)n * HDIM + lane]      = h0[i];
            g_h[(size_t)n * HDIM + 32 + lane] = h1[i];
        }
    }
    __syncthreads();

#pragma unroll
    for (int i = 0; i < 4; i++) {
        sbuf[lane * 36 + nb + i]        = h0[i];
        sbuf[(lane + 32) * 36 + nb + i] = h1[i];
    }
    __syncthreads();

    if (!LAST) {
        float pacc[4];
        float bb = __ldg(&b1n[lane]);
#pragma unroll
        for (int i = 0; i < 4; i++) pacc[i] = bb;
#pragma unroll
        for (int k = 0; k < 64; k++) {
            float4 hv = *(const float4*)&sbuf[k * 36 + nb];
            float wk = __ldg(&w1n[k * HH + lane]);
            pacc[0] = fmaf(hv.x, wk, pacc[0]);
            pacc[1] = fmaf(hv.y, wk, pacc[1]);
            pacc[2] = fmaf(hv.z, wk, pacc[2]);
            pacc[3] = fmaf(hv.w, wk, pacc[3]);
        }
        float* gp = (float*)g_p4;
#pragma unroll
        for (int i = 0; i < 4; i++)
            if ((nb + i) < rem) gp[(size_t)(n0 + nb + i) * HH + lane] = pacc[i];
    } else {
        float da[4], va[4];
        float dbi = __ldg(&db1[lane]), vbi = __ldg(&vb1[lane]);
#pragma unroll
        for (int i = 0; i < 4; i++) { da[i] = dbi; va[i] = vbi; }
#pragma unroll
        for (int k = 0; k < 64; k++) {
            float4 hv = *(const float4*)&sbuf[k * 36 + nb];
            float dwk = __ldg(&dw1[k * HH + lane]);
            float vwk = __ldg(&vw1[k * HH + lane]);
            da[0] = fmaf(hv.x, dwk, da[0]); va[0] = fmaf(hv.x, vwk, va[0]);
            da[1] = fmaf(hv.y, dwk, da[1]); va[1] = fmaf(hv.y, vwk, va[1]);
            da[2] = fmaf(hv.z, dwk, da[2]); va[2] = fmaf(hv.z, vwk, va[2]);
            da[3] = fmaf(hv.w, dwk, da[3]); va[3] = fmaf(hv.w, vwk, va[3]);
        }
        float w2d  = __ldg(&dw2[lane]);
        float w2v0 = __ldg(&vw2[lane * 2 + 0]);
        float w2v1 = __ldg(&vw2[lane * 2 + 1]);
#pragma unroll
        for (int i = 0; i < 4; i++) {
            float rd = fmaxf(da[i], 0.f), rv = fmaxf(va[i], 0.f);
            float d  = rd * w2d;
            float v0 = rv * w2v0;
            float v1 = rv * w2v1;
#pragma unroll
            for (int o = 16; o; o >>= 1) {
                d  += __shfl_xor_sync(FULL, d, o);
                v0 += __shfl_xor_sync(FULL, v0, o);
                v1 += __shfl_xor_sync(FULL, v1, o);
            }
            int n = n0 + nb + i;
            if (lane == 0 && (nb + i) < rem) {
                out[n] = d + __ldg(&db2[0]);
                float2* vout = (float2*)(out + N_NODES);
                vout[n] = make_float2(v0 + __ldg(&vb2[0]), v1 + __ldg(&vb2[1]));
            }
        }
    }
}

// ---------------- launch ----------------
extern "C" void kernel_launch(void* const* d_in, const int* in_sizes, int n_in,
                              void* d_out, int out_size)
{
    const float* x       = (const float*)d_in[0];
    const int*   ei      = (const int*)  d_in[1];
    const float* ea      = (const float*)d_in[2];
    const float* enc_w   = (const float*)d_in[3];
    const float* enc_b   = (const float*)d_in[4];
    const float* enc_g   = (const float*)d_in[5];
    const float* enc_bt  = (const float*)d_in[6];
    const float* mlp_w1  = (const float*)d_in[7];   // [L, 67, 32]
    const float* mlp_b1  = (const float*)d_in[8];   // [L, 32]
    const float* mlp_w2  = (const float*)d_in[9];   // [L, 32, 64]
    const float* mlp_b2  = (const float*)d_in[10];  // [L, 64]
    const float* ln_g    = (const float*)d_in[11];  // [L, 64]
    const float* ln_b    = (const float*)d_in[12];  // [L, 64]
    const float* dw1     = (const float*)d_in[13];
    const float* db1     = (const float*)d_in[14];
    const float* dw2     = (const float*)d_in[15];
    const float* db2     = (const float*)d_in[16];
    const float* vw1     = (const float*)d_in[17];
    const float* vb1     = (const float*)d_in[18];
    const float* vw2     = (const float*)d_in[19];
    const float* vb2     = (const float*)d_in[20];
    float* out = (float*)d_out;

    const int TB = 256;
    const int enc_grid  = (N_NODES / 4 * 32 + TB - 1) / TB;   // 4 nodes/warp
    const int node_grid = (N_NODES + 31) / 32;                // 32 nodes/block
    const int gath_grid = (N_NODES * 32 + TB - 1) / TB;       // warp/node
    const int eTB_grid  = (E_EDGES + TB - 1) / TB;

    encoder_kernel<<<enc_grid, TB>>>(x, enc_w, enc_b, enc_g, enc_bt,
                                     mlp_w1, mlp_b1);
    count_kernel<<<eTB_grid, TB>>>(ei);
    zero_total_kernel<<<1, 32>>>();
    assign_kernel<<<(N_NODES + TB - 1) / TB, TB>>>();
    bucket_kernel<<<eTB_grid, TB>>>(ei, ea);

    for (int i = 0; i < NLAYERS; i++) {
        const float* w1 = mlp_w1 + (size_t)i * (HDIM + 3) * HH;
        const float* w2 = mlp_w2 + (size_t)i * HH * HDIM;
        const float* b2 = mlp_b2 + (size_t)i * HDIM;
        const float* lg = ln_g   + (size_t)i * HDIM;
        const float* lb = ln_b   + (size_t)i * HDIM;
        const float* w1n = mlp_w1 + (size_t)(i + 1) * (HDIM + 3) * HH;
        const float* b1n = mlp_b1 + (size_t)(i + 1) * HH;

        edge_gather_kernel<<<gath_grid, TB>>>(w1);

        if (i + 1 < NLAYERS)
            node_agg_kernel<false><<<node_grid, TB>>>(w2, b2, lg, lb, w1n, b1n,
                dw1, db1, dw2, db2, vw1, vb1, vw2, vb2, out);
        else
            node_agg_kernel<true ><<<node_grid, TB>>>(w2, b2, lg, lb, nullptr, nullptr,
                dw1, db1, dw2, db2, vw1, vb1, vw2, vb2, out);
    }
}